// round 3
// baseline (speedup 1.0000x reference)
#include <cuda_runtime.h>

#define HWSZ 65536           // 256*256
#define FEAT (16*64*HWSZ)    // 67,108,864 floats = 256 MB

// scratch feature maps (allocation-free: __device__ globals)
__device__ float g_featA[FEAT];
__device__ float g_featB[FEAT];

__device__ __forceinline__ float prelu_f(float v, float a) {
    return v >= 0.f ? v : a * v;
}

// ---- packed f32x2 helpers (sm_103a) --------------------------------------
__device__ __forceinline__ unsigned long long splat2(float v) {
    unsigned long long r;
    asm("mov.b64 %0, {%1, %1};" : "=l"(r) : "f"(v));
    return r;
}
__device__ __forceinline__ void fma2(unsigned long long& d,
                                     unsigned long long a,
                                     unsigned long long b) {
    asm("fma.rn.f32x2 %0, %1, %2, %0;" : "+l"(d) : "l"(a), "l"(b));
}
__device__ __forceinline__ void unpack2(unsigned long long v, float& lo, float& hi) {
    asm("mov.b64 {%0, %1}, %2;" : "=f"(lo), "=f"(hi) : "l"(v));
}

// ---------------------------------------------------------------------------
// CS sampling conv: outcsy[n,f,by,bx] = sum_{i,j} x[n, by*32+i, bx*32+j]*Wcs[f,i,j]
// ---------------------------------------------------------------------------
__global__ void cs_kernel(const float* __restrict__ x,
                          const float* __restrict__ Wcs,
                          float* __restrict__ csy) {
    const int pg = blockIdx.x;   // by
    const int n  = blockIdx.y;
    const int f  = threadIdx.x;
    __shared__ float sX[8][32];
    __shared__ float sW[256][33];

    float acc[8] = {0.f,0.f,0.f,0.f,0.f,0.f,0.f,0.f};

    for (int k0 = 0; k0 < 1024; k0 += 32) {
        const int i = k0 >> 5;  // row within 32x32 block
        {
            int p = threadIdx.x >> 5, kk = threadIdx.x & 31;
            sX[p][kk] = x[n * HWSZ + (pg * 32 + i) * 256 + p * 32 + kk];
        }
        for (int e = threadIdx.x; e < 8192; e += 256) {
            int ff = e >> 5, kk = e & 31;
            sW[ff][kk] = Wcs[ff * 1024 + k0 + kk];
        }
        __syncthreads();
#pragma unroll
        for (int kk = 0; kk < 32; kk++) {
            float w = sW[f][kk];
#pragma unroll
            for (int p = 0; p < 8; p++) acc[p] += sX[p][kk] * w;
        }
        __syncthreads();
    }
#pragma unroll
    for (int p = 0; p < 8; p++)
        csy[(n * 256 + f) * 64 + pg * 8 + p] = acc[p];
}

// ---------------------------------------------------------------------------
// Init reconstruction (1x1 conv 256->1024) fused with depth-to-space scatter.
// ---------------------------------------------------------------------------
__global__ void init_kernel(const float* __restrict__ csy,
                            const float* __restrict__ Wi,
                            float* __restrict__ initrec) {
    const int cb = blockIdx.x * 128;
    const int n  = blockIdx.y;
    const int cg  = threadIdx.x >> 3;  // 0..31 (4 channels each)
    const int pgl = threadIdx.x & 7;   // 0..7  (8 positions each)
    __shared__ float sX[32][64];
    __shared__ float sW[128][33];

    float acc[4][8] = {};

    for (int k0 = 0; k0 < 256; k0 += 32) {
        for (int e = threadIdx.x; e < 2048; e += 256) {
            int kk = e >> 6, pos = e & 63;
            sX[kk][pos] = csy[(n * 256 + k0 + kk) * 64 + pos];
        }
        for (int e = threadIdx.x; e < 4096; e += 256) {
            int cl = e >> 5, kk = e & 31;
            sW[cl][kk] = Wi[(cb + cl) * 256 + k0 + kk];
        }
        __syncthreads();
#pragma unroll
        for (int kk = 0; kk < 32; kk++) {
            float w0 = sW[cg * 4 + 0][kk];
            float w1 = sW[cg * 4 + 1][kk];
            float w2 = sW[cg * 4 + 2][kk];
            float w3 = sW[cg * 4 + 3][kk];
#pragma unroll
            for (int pp = 0; pp < 8; pp++) {
                float xv = sX[kk][pgl * 8 + pp];
                acc[0][pp] += w0 * xv;
                acc[1][pp] += w1 * xv;
                acc[2][pp] += w2 * xv;
                acc[3][pp] += w3 * xv;
            }
        }
        __syncthreads();
    }
#pragma unroll
    for (int jc = 0; jc < 4; jc++) {
        int c  = cb + cg * 4 + jc;
        int jj = c >> 5;
        int ii = c & 31;
#pragma unroll
        for (int pp = 0; pp < 8; pp++) {
            int pos = pgl * 8 + pp;
            int by = pos >> 3, bx = pos & 7;
            initrec[n * HWSZ + (by * 32 + ii) * 256 + (bx * 32 + jj)] = acc[jc][pp];
        }
    }
}

// ---------------------------------------------------------------------------
// First conv: 1 -> 64 channels, 3x3 pad 1, PReLU(a_main)
// ---------------------------------------------------------------------------
__global__ void first_kernel(const float* __restrict__ initrec,
                             const float* __restrict__ Wf,
                             const float* __restrict__ aM,
                             float* __restrict__ out) {
    const int tx = blockIdx.x, ty = blockIdx.y, n = blockIdx.z;
    __shared__ float sI[18][18];
    __shared__ float sWf[576];

    for (int e = threadIdx.x; e < 324; e += 256) {
        int yy = e / 18, xx = e % 18;
        int gy = ty * 16 - 1 + yy, gx = tx * 16 - 1 + xx;
        float v = 0.f;
        if ((unsigned)gy < 256u && (unsigned)gx < 256u)
            v = initrec[n * HWSZ + gy * 256 + gx];
        sI[yy][xx] = v;
    }
    for (int e = threadIdx.x; e < 576; e += 256) sWf[e] = Wf[e];
    __syncthreads();

    const float a = aM[0];
    const int r = threadIdx.x >> 4, c = threadIdx.x & 15;
    float v[9];
#pragma unroll
    for (int ky = 0; ky < 3; ky++)
#pragma unroll
        for (int kx = 0; kx < 3; kx++)
            v[ky * 3 + kx] = sI[r + ky][c + kx];

    const int gy = ty * 16 + r, gx = tx * 16 + c;
    for (int co = 0; co < 64; co++) {
        float s = 0.f;
#pragma unroll
        for (int kk = 0; kk < 9; kk++) s += sWf[co * 9 + kk] * v[kk];
        out[((n * 64 + co) << 16) + (gy << 8) + gx] = prelu_f(s, a);
    }
}

// ---------------------------------------------------------------------------
// Main 64->64 3x3 conv, pad 1.  16x16 spatial tile x all 64 co, one n per CTA.
// Thread: 16 co x 4 px register tile, with co packed in f32x2 PAIRS so each
// fma.rn.f32x2 does 2 FMAs in one issue slot. Weights come pre-packed from
// smem (co contiguous); only 6 input splats per (ci,ky).
// RES=false: out = prelu(conv(in), a)
// RES=true : out = prelu(res + conv(in), a)   (res may alias out)
// ---------------------------------------------------------------------------
template <bool RES>
__global__ void __launch_bounds__(256, 2) blk_kernel(
    const float* __restrict__ in, const float* __restrict__ Wb,
    const float* __restrict__ aB, float* __restrict__ out,
    const float* __restrict__ res) {
    const int tx = blockIdx.x, ty = blockIdx.y, n = blockIdx.z;
    __shared__ float sIn[8][18][20];       // [ci][y][x], x padded to 20
    __shared__ float sW[8 * 9 * 68];       // [ci][kk][co], co padded to 68 (16B rows)

    const int cog = threadIdx.x >> 6;          // 0..3
    const int pix = threadIdx.x & 63;          // 0..63
    const int row = pix >> 2;                  // 0..15
    const int col0 = (pix & 3) << 2;           // 0,4,8,12
    const int cobase = cog << 4;               // 0,16,32,48

    // acc2[c2][p] holds fp32 pair (co=cobase+2*c2, co=cobase+2*c2+1) at pixel p
    unsigned long long acc2[8][4];
#pragma unroll
    for (int c = 0; c < 8; c++)
#pragma unroll
        for (int p = 0; p < 4; p++) acc2[c][p] = 0ull;

    for (int ci0 = 0; ci0 < 64; ci0 += 8) {
        for (int e = threadIdx.x; e < 2592; e += 256) {
            int ci = e / 324, r2 = e % 324, yy = r2 / 18, xx = r2 % 18;
            int gy = ty * 16 - 1 + yy, gx = tx * 16 - 1 + xx;
            float v = 0.f;
            if ((unsigned)gy < 256u && (unsigned)gx < 256u)
                v = in[((n * 64 + ci0 + ci) << 16) + (gy << 8) + gx];
            sIn[ci][yy][xx] = v;
        }
        for (int e = threadIdx.x; e < 4608; e += 256) {
            int co = e / 72, r2 = e % 72, ci = r2 / 9, kk = r2 % 9;
            sW[(ci * 9 + kk) * 68 + co] = Wb[co * 576 + (ci0 + ci) * 9 + kk];
        }
        __syncthreads();

#pragma unroll 1
        for (int ci = 0; ci < 8; ci++) {
            const float* wbase = &sW[ci * 9 * 68 + cobase];
#pragma unroll
            for (int ky = 0; ky < 3; ky++) {
                const float* ip = &sIn[ci][row + ky][col0];
                float4 i0 = *reinterpret_cast<const float4*>(ip);
                float2 i1 = *reinterpret_cast<const float2*>(ip + 4);
                unsigned long long ivp[6];
                ivp[0] = splat2(i0.x); ivp[1] = splat2(i0.y);
                ivp[2] = splat2(i0.z); ivp[3] = splat2(i0.w);
                ivp[4] = splat2(i1.x); ivp[5] = splat2(i1.y);
#pragma unroll
                for (int kx = 0; kx < 3; kx++) {
                    // 8 packed weight pairs = 64B, loaded as 4x 16B
                    const ulonglong2* wp = reinterpret_cast<const ulonglong2*>(
                        wbase + (ky * 3 + kx) * 68);
                    ulonglong2 wa = wp[0], wb2 = wp[1], wc = wp[2], wd = wp[3];
                    unsigned long long w[8] = {wa.x, wa.y, wb2.x, wb2.y,
                                               wc.x, wc.y, wd.x, wd.y};
#pragma unroll
                    for (int c = 0; c < 8; c++) {
                        fma2(acc2[c][0], w[c], ivp[kx + 0]);
                        fma2(acc2[c][1], w[c], ivp[kx + 1]);
                        fma2(acc2[c][2], w[c], ivp[kx + 2]);
                        fma2(acc2[c][3], w[c], ivp[kx + 3]);
                    }
                }
            }
        }
        __syncthreads();
    }

    const float a = aB[0];
    const int gy = ty * 16 + row, gx0 = tx * 16 + col0;
#pragma unroll
    for (int c2 = 0; c2 < 8; c2++) {
        float lo[4], hi[4];
#pragma unroll
        for (int p = 0; p < 4; p++) unpack2(acc2[c2][p], lo[p], hi[p]);

        int baseL = ((n * 64 + cobase + 2 * c2 + 0) << 16) + (gy << 8) + gx0;
        int baseH = ((n * 64 + cobase + 2 * c2 + 1) << 16) + (gy << 8) + gx0;

        float4 vL = make_float4(lo[0], lo[1], lo[2], lo[3]);
        float4 vH = make_float4(hi[0], hi[1], hi[2], hi[3]);
        if (RES) {
            float4 rL = *reinterpret_cast<const float4*>(res + baseL);
            float4 rH = *reinterpret_cast<const float4*>(res + baseH);
            vL.x += rL.x; vL.y += rL.y; vL.z += rL.z; vL.w += rL.w;
            vH.x += rH.x; vH.y += rH.y; vH.z += rH.z; vH.w += rH.w;
        }
        vL.x = prelu_f(vL.x, a); vL.y = prelu_f(vL.y, a);
        vL.z = prelu_f(vL.z, a); vL.w = prelu_f(vL.w, a);
        vH.x = prelu_f(vH.x, a); vH.y = prelu_f(vH.y, a);
        vH.z = prelu_f(vH.z, a); vH.w = prelu_f(vH.w, a);
        *reinterpret_cast<float4*>(out + baseL) = vL;
        *reinterpret_cast<float4*>(out + baseH) = vH;
    }
}

// ---------------------------------------------------------------------------
// Last conv: (feat + initrec broadcast) -> 1 channel, 3x3 pad 1.
// ---------------------------------------------------------------------------
__global__ void last_kernel(const float* __restrict__ feat,
                            const float* __restrict__ initrec,
                            const float* __restrict__ Wl,
                            float* __restrict__ out) {
    const int tx = blockIdx.x, ty = blockIdx.y, n = blockIdx.z;
    __shared__ float sInit[18][18];
    __shared__ float sIn[8][18][20];
    __shared__ float sWl[576];

    for (int e = threadIdx.x; e < 324; e += 256) {
        int yy = e / 18, xx = e % 18;
        int gy = ty * 16 - 1 + yy, gx = tx * 16 - 1 + xx;
        float v = 0.f;
        if ((unsigned)gy < 256u && (unsigned)gx < 256u)
            v = initrec[n * HWSZ + gy * 256 + gx];
        sInit[yy][xx] = v;
    }
    for (int e = threadIdx.x; e < 576; e += 256) sWl[e] = Wl[e];
    __syncthreads();

    const int r = threadIdx.x >> 4, c = threadIdx.x & 15;
    float acc = 0.f;

    for (int ci0 = 0; ci0 < 64; ci0 += 8) {
        for (int e = threadIdx.x; e < 2592; e += 256) {
            int ci = e / 324, r2 = e % 324, yy = r2 / 18, xx = r2 % 18;
            int gy = ty * 16 - 1 + yy, gx = tx * 16 - 1 + xx;
            float v = 0.f;
            if ((unsigned)gy < 256u && (unsigned)gx < 256u)
                v = feat[((n * 64 + ci0 + ci) << 16) + (gy << 8) + gx];
            sIn[ci][yy][xx] = v + sInit[yy][xx];
        }
        __syncthreads();
#pragma unroll 1
        for (int ci = 0; ci < 8; ci++) {
#pragma unroll
            for (int ky = 0; ky < 3; ky++)
#pragma unroll
                for (int kx = 0; kx < 3; kx++)
                    acc += sIn[ci][r + ky][c + kx] * sWl[(ci0 + ci) * 9 + ky * 3 + kx];
        }
        __syncthreads();
    }
    out[n * HWSZ + (ty * 16 + r) * 256 + (tx * 16 + c)] = acc;
}

// ---------------------------------------------------------------------------
extern "C" void kernel_launch(void* const* d_in, const int* in_sizes, int n_in,
                              void* d_out, int out_size) {
    (void)in_sizes; (void)n_in; (void)out_size;
    const float* x   = (const float*)d_in[0];
    const float* Wcs = (const float*)d_in[1];
    const float* Wi  = (const float*)d_in[2];
    const float* Wf  = (const float*)d_in[3];
    const float* Wb  = (const float*)d_in[4];
    const float* Wl  = (const float*)d_in[5];
    const float* aM  = (const float*)d_in[6];
    const float* aB  = (const float*)d_in[7];

    float* out     = (float*)d_out;             // [16,1,256,256]
    float* csy     = out + 16 * HWSZ;           // [16,256,8,8]
    float* initrec = csy + 16 * 256 * 64;       // [16,1,256,256]

    float *fA = nullptr, *fB = nullptr;
    cudaGetSymbolAddress((void**)&fA, g_featA);
    cudaGetSymbolAddress((void**)&fB, g_featB);

    cs_kernel<<<dim3(8, 16), 256>>>(x, Wcs, csy);
    init_kernel<<<dim3(8, 16), 256>>>(csy, Wi, initrec);
    first_kernel<<<dim3(16, 16, 16), 256>>>(initrec, Wf, aM, fA);

    for (int i = 0; i < 4; i++) {
        blk_kernel<false><<<dim3(16, 16, 16), 256>>>(fA, Wb, aB, fB, nullptr);
        blk_kernel<true><<<dim3(16, 16, 16), 256>>>(fB, Wb, aB, fA, fA);
    }
    last_kernel<<<dim3(16, 16, 16), 256>>>(fA, initrec, Wl, out);
}

// round 5
// speedup vs baseline: 1.2801x; 1.2801x over previous
#include <cuda_runtime.h>
#include <cuda_bf16.h>
#include <cstdint>

#define HWSZ 65536
#define FEAT (16*64*HWSZ)           // floats; reused as 2 bf16 planes (hi, lo)
#define PLANE ((size_t)16*HWSZ*64)  // elements per bf16 plane

__device__ float g_featA[FEAT];
__device__ float g_featB[FEAT];
__device__ __nv_bfloat16 g_wblk[9 * 64 * 200];   // [tap][co][K 192 pad 200]

__device__ __forceinline__ float prelu_f(float v, float a) { return v >= 0.f ? v : a * v; }

__device__ __forceinline__ uint32_t smem_u32(const void* p) {
    uint32_t a;
    asm("{ .reg .u64 t; cvta.to.shared.u64 t, %1; cvt.u32.u64 %0, t; }" : "=r"(a) : "l"(p));
    return a;
}
__device__ __forceinline__ void ldsm4(uint32_t* r, uint32_t addr) {
    asm volatile("ldmatrix.sync.aligned.m8n8.x4.shared.b16 {%0,%1,%2,%3}, [%4];"
                 : "=r"(r[0]), "=r"(r[1]), "=r"(r[2]), "=r"(r[3]) : "r"(addr));
}
__device__ __forceinline__ void mma16816(float* d, const uint32_t* a, uint32_t b0, uint32_t b1) {
    asm volatile("mma.sync.aligned.m16n8k16.row.col.f32.bf16.bf16.f32 "
                 "{%0,%1,%2,%3},{%4,%5,%6,%7},{%8,%9},{%0,%1,%2,%3};"
                 : "+f"(d[0]), "+f"(d[1]), "+f"(d[2]), "+f"(d[3])
                 : "r"(a[0]), "r"(a[1]), "r"(a[2]), "r"(a[3]), "r"(b0), "r"(b1));
}
__device__ __forceinline__ void cpa16(uint32_t dst, const void* src, int sz) {
    asm volatile("cp.async.cg.shared.global [%0], [%1], 16, %2;" :: "r"(dst), "l"(src), "r"(sz));
}
__device__ __forceinline__ void cpa16f(uint32_t dst, const void* src) {
    asm volatile("cp.async.cg.shared.global [%0], [%1], 16;" :: "r"(dst), "l"(src));
}
#define CPA_COMMIT() asm volatile("cp.async.commit_group;")
#define CPA_WAIT(n)  asm volatile("cp.async.wait_group %0;" :: "n"(n))

// ---- weight prep: Wb fp32 -> [tap][co][200] bf16 (K: 64 wh | 64 wl | 64 wh) ----
__global__ void wprep_kernel(const float* __restrict__ Wb, __nv_bfloat16* __restrict__ wblk) {
    int i = blockIdx.x * 256 + threadIdx.x;
    if (i >= 9 * 64 * 200) return;
    int k = i % 200, co = (i / 200) % 64, tap = i / (200 * 64);
    int ky = tap / 3, kx = tap % 3;
    __nv_bfloat16 v = __float2bfloat16(0.f);
    if (k < 192) {
        int ci = k & 63, seg = k >> 6;
        float w = Wb[co * 576 + ci * 9 + ky * 3 + kx];
        __nv_bfloat16 h = __float2bfloat16(w);
        v = (seg == 1) ? __float2bfloat16(w - __bfloat162float(h)) : h;
    }
    wblk[i] = v;
}

// ---------------- CS sampling conv (fp32) ----------------------------------
__global__ void cs_kernel(const float* __restrict__ x, const float* __restrict__ Wcs,
                          float* __restrict__ csy) {
    const int pg = blockIdx.x, n = blockIdx.y, f = threadIdx.x;
    __shared__ float sX[8][32];
    __shared__ float sW[256][33];
    float acc[8] = {};
    for (int k0 = 0; k0 < 1024; k0 += 32) {
        const int i = k0 >> 5;
        int p = threadIdx.x >> 5, kk = threadIdx.x & 31;
        sX[p][kk] = x[n * HWSZ + (pg * 32 + i) * 256 + p * 32 + kk];
        for (int e = threadIdx.x; e < 8192; e += 256)
            sW[e >> 5][e & 31] = Wcs[(e >> 5) * 1024 + k0 + (e & 31)];
        __syncthreads();
#pragma unroll
        for (int q = 0; q < 32; q++) {
            float w = sW[f][q];
#pragma unroll
            for (int pp = 0; pp < 8; pp++) acc[pp] += sX[pp][q] * w;
        }
        __syncthreads();
    }
#pragma unroll
    for (int pp = 0; pp < 8; pp++) csy[(n * 256 + f) * 64 + pg * 8 + pp] = acc[pp];
}

// ---------------- init reconstruction (fp32) -------------------------------
__global__ void init_kernel(const float* __restrict__ csy, const float* __restrict__ Wi,
                            float* __restrict__ initrec) {
    const int cb = blockIdx.x * 128, n = blockIdx.y;
    const int cg = threadIdx.x >> 3, pgl = threadIdx.x & 7;
    __shared__ float sX[32][64];
    __shared__ float sW[128][33];
    float acc[4][8] = {};
    for (int k0 = 0; k0 < 256; k0 += 32) {
        for (int e = threadIdx.x; e < 2048; e += 256)
            sX[e >> 6][e & 63] = csy[(n * 256 + k0 + (e >> 6)) * 64 + (e & 63)];
        for (int e = threadIdx.x; e < 4096; e += 256)
            sW[e >> 5][e & 31] = Wi[(cb + (e >> 5)) * 256 + k0 + (e & 31)];
        __syncthreads();
#pragma unroll
        for (int kk = 0; kk < 32; kk++) {
            float w0 = sW[cg*4+0][kk], w1 = sW[cg*4+1][kk], w2 = sW[cg*4+2][kk], w3 = sW[cg*4+3][kk];
#pragma unroll
            for (int pp = 0; pp < 8; pp++) {
                float xv = sX[kk][pgl * 8 + pp];
                acc[0][pp] += w0*xv; acc[1][pp] += w1*xv; acc[2][pp] += w2*xv; acc[3][pp] += w3*xv;
            }
        }
        __syncthreads();
    }
#pragma unroll
    for (int jc = 0; jc < 4; jc++) {
        int c = cb + cg * 4 + jc, jj = c >> 5, ii = c & 31;
#pragma unroll
        for (int pp = 0; pp < 8; pp++) {
            int pos = pgl * 8 + pp, by = pos >> 3, bx = pos & 7;
            initrec[n * HWSZ + (by * 32 + ii) * 256 + (bx * 32 + jj)] = acc[jc][pp];
        }
    }
}

// ------- first conv 1->64 + PReLU -> hi/lo bf16 planes (coalesced) ---------
__global__ void first_kernel(const float* __restrict__ initrec, const float* __restrict__ Wf,
                             const float* __restrict__ aM,
                             __nv_bfloat16* __restrict__ outH, __nv_bfloat16* __restrict__ outL) {
    const int tx = blockIdx.x, ty = blockIdx.y, n = blockIdx.z;
    __shared__ float sI[18][18];
    __shared__ float sWf[576];
    for (int e = threadIdx.x; e < 324; e += 256) {
        int yy = e / 18, xx = e % 18, gy = ty * 16 - 1 + yy, gx = tx * 16 - 1 + xx;
        sI[yy][xx] = ((unsigned)gy < 256u && (unsigned)gx < 256u) ? initrec[n * HWSZ + gy * 256 + gx] : 0.f;
    }
    for (int e = threadIdx.x; e < 576; e += 256) sWf[e] = Wf[e];
    __syncthreads();
    const float a = aM[0];
    const int co = threadIdx.x & 63, pl = threadIdx.x >> 6;
    float wr[9];
#pragma unroll
    for (int k = 0; k < 9; k++) wr[k] = sWf[co * 9 + k];
    for (int pxi = 0; pxi < 64; pxi++) {
        int px = pxi * 4 + pl, r = px >> 4, c = px & 15;
        float s = 0.f;
#pragma unroll
        for (int ky = 0; ky < 3; ky++)
#pragma unroll
            for (int kx = 0; kx < 3; kx++) s += wr[ky * 3 + kx] * sI[r + ky][c + kx];
        s = prelu_f(s, a);
        __nv_bfloat16 h = __float2bfloat16(s);
        __nv_bfloat16 l = __float2bfloat16(s - __bfloat162float(h));
        size_t ad = ((size_t)(n * HWSZ + (ty * 16 + r) * 256 + tx * 16 + c)) * 64 + co;
        outH[ad] = h;
        outL[ad] = l;
    }
}

// ---------- res-block conv 64->64 via mma.sync bf16 split ------------------
// grid (512, 16): blockIdx.x -> (y = bx>>1, x0 = (bx&1)*128). 256 thr, 8 warps.
// smem: slab hi [3][130][72] bf16, slab lo same, B double-buffer 2x[64][200] bf16.
#define SA_H 0
#define SA_L 56160
#define SB0  112320
#define SBSZ 25600
#define SMEM_BLK (SB0 + 2 * SBSZ)   // 163,520 B

template <bool RES>
__global__ void __launch_bounds__(256, 1) blk_mma(
    const __nv_bfloat16* __restrict__ inH, const __nv_bfloat16* __restrict__ inL,
    const __nv_bfloat16* __restrict__ wblk, const float* __restrict__ aB,
    __nv_bfloat16* __restrict__ outH, __nv_bfloat16* __restrict__ outL) {
    extern __shared__ unsigned char sm[];
    const uint32_t sb = smem_u32(sm);
    const int tid = threadIdx.x, w = tid >> 5, lane = tid & 31;
    const int n = blockIdx.y, y = blockIdx.x >> 1, x0 = (blockIdx.x & 1) * 128;

    // slab copy: 3 rows x 130 px x 8 chunks x 2 planes (zero-fill OOB)
    for (int idx = tid; idx < 6240; idx += 256) {
        int plane = idx >= 3120;
        int i2 = plane ? idx - 3120 : idx;
        int row = i2 / 1040, r2 = i2 - row * 1040, px = r2 >> 3, ch = r2 & 7;
        int ys = y - 1 + row, gxs = x0 - 1 + px;
        bool ok = (unsigned)ys < 256u && (unsigned)gxs < 256u;
        const __nv_bfloat16* base = plane ? inL : inH;
        const __nv_bfloat16* sp = ok ? base + ((size_t)(n * HWSZ + ys * 256 + gxs)) * 64 + ch * 8 : base;
        uint32_t dst = sb + (plane ? SA_L : SA_H) + ((row * 130 + px) * 72 + ch * 8) * 2;
        cpa16(dst, sp, ok ? 16 : 0);
    }
    CPA_COMMIT();
    // B tap0
    {
        const uint4* s = (const uint4*)wblk;
        for (int i = tid; i < 1600; i += 256) cpa16f(sb + SB0 + i * 16, s + i);
    }
    CPA_COMMIT();

    float d[8][4];
#pragma unroll
    for (int i = 0; i < 8; i++)
#pragma unroll
        for (int j = 0; j < 4; j++) d[i][j] = 0.f;

    for (int tap = 0; tap < 9; tap++) {
        if (tap < 8) {
            const uint4* s = (const uint4*)(wblk + (tap + 1) * 12800);
            uint32_t db = sb + SB0 + ((tap + 1) & 1) * SBSZ;
            for (int i = tid; i < 1600; i += 256) cpa16f(db + i * 16, s + i);
            CPA_COMMIT();
            CPA_WAIT(1);
        } else {
            CPA_WAIT(0);
        }
        __syncthreads();

        const int ky = tap / 3, kx = tap % 3;
        // A fragments (Ah reused for wl term)
        uint32_t ah[4][4], al[4][4];
        {
            uint32_t rowoff = (uint32_t)((ky * 130 + w * 16 + kx) + (lane & 15)) * 144 +
                              ((lane >> 4) & 1) * 16;
            uint32_t aH = sb + SA_H + rowoff;
            uint32_t aL = sb + SA_L + rowoff;
#pragma unroll
            for (int q = 0; q < 4; q++) {
                ldsm4(ah[q], aH + q * 32);
                ldsm4(al[q], aL + q * 32);
            }
        }
        uint32_t bB = sb + SB0 + (tap & 1) * SBSZ + (lane & 7) * 400 +
                      ((lane >> 4) & 1) * 3200 + ((lane >> 3) & 1) * 16;
#pragma unroll
        for (int ks = 0; ks < 12; ks++) {
            const uint32_t* af = (ks < 4) ? ah[ks] : ((ks < 8) ? ah[ks - 4] : al[ks - 8]);
            uint32_t bk = bB + ks * 32;
#pragma unroll
            for (int np = 0; np < 4; np++) {
                uint32_t b[4];
                ldsm4(b, bk + np * 6400);
                mma16816(d[np * 2 + 0], af, b[0], b[1]);
                mma16816(d[np * 2 + 1], af, b[2], b[3]);
            }
        }
        __syncthreads();
    }

    // epilogue: residual + PReLU + split store
    const float a = aB[0];
    const int g = lane >> 2, q2 = lane & 3;
    const size_t pixbase = (size_t)(n * HWSZ + y * 256 + x0 + w * 16);
#pragma unroll
    for (int half = 0; half < 2; half++) {
        size_t pa = (pixbase + g + half * 8) * 64;
#pragma unroll
        for (int nt = 0; nt < 8; nt++) {
            int co = nt * 8 + q2 * 2;
            float v0 = d[nt][half * 2 + 0], v1 = d[nt][half * 2 + 1];
            if (RES) {
                uint32_t h2 = *(const uint32_t*)(outH + pa + co);
                uint32_t l2 = *(const uint32_t*)(outL + pa + co);
                v0 += __bfloat162float(__ushort_as_bfloat16((unsigned short)(h2 & 0xffff))) +
                      __bfloat162float(__ushort_as_bfloat16((unsigned short)(l2 & 0xffff)));
                v1 += __bfloat162float(__ushort_as_bfloat16((unsigned short)(h2 >> 16))) +
                      __bfloat162float(__ushort_as_bfloat16((unsigned short)(l2 >> 16)));
            }
            v0 = prelu_f(v0, a);
            v1 = prelu_f(v1, a);
            __nv_bfloat16 h0 = __float2bfloat16(v0), h1 = __float2bfloat16(v1);
            __nv_bfloat16 l0 = __float2bfloat16(v0 - __bfloat162float(h0));
            __nv_bfloat16 l1 = __float2bfloat16(v1 - __bfloat162float(h1));
            uint32_t hp = (uint32_t)__bfloat16_as_ushort(h0) | ((uint32_t)__bfloat16_as_ushort(h1) << 16);
            uint32_t lp = (uint32_t)__bfloat16_as_ushort(l0) | ((uint32_t)__bfloat16_as_ushort(l1) << 16);
            *(uint32_t*)(outH + pa + co) = hp;
            *(uint32_t*)(outL + pa + co) = lp;
        }
    }
}

// --------- last conv: (feat planes + initrec) -> 1 channel -----------------
__global__ void last_kernel(const __nv_bfloat16* __restrict__ featH,
                            const __nv_bfloat16* __restrict__ featL,
                            const float* __restrict__ initrec,
                            const float* __restrict__ Wl, float* __restrict__ out) {
    const int tx = blockIdx.x, ty = blockIdx.y, n = blockIdx.z;
    __shared__ float sInit[18][18];
    __shared__ float sIn[8][18][20];
    __shared__ float sWl[576];
    for (int e = threadIdx.x; e < 324; e += 256) {
        int yy = e / 18, xx = e % 18, gy = ty * 16 - 1 + yy, gx = tx * 16 - 1 + xx;
        sInit[yy][xx] = ((unsigned)gy < 256u && (unsigned)gx < 256u) ? initrec[n * HWSZ + gy * 256 + gx] : 0.f;
    }
    for (int e = threadIdx.x; e < 576; e += 256) sWl[e] = Wl[e];
    __syncthreads();
    const int r = threadIdx.x >> 4, c = threadIdx.x & 15;
    float acc = 0.f;
    for (int ci0 = 0; ci0 < 64; ci0 += 8) {
        for (int e = threadIdx.x; e < 2592; e += 256) {
            int px = e >> 3, ci = e & 7, yy = px / 18, xx = px % 18;
            int gy = ty * 16 - 1 + yy, gx = tx * 16 - 1 + xx;
            float v = 0.f;
            if ((unsigned)gy < 256u && (unsigned)gx < 256u) {
                size_t ad = (size_t)(n * HWSZ + gy * 256 + gx) * 64 + ci0 + ci;
                v = __bfloat162float(featH[ad]) + __bfloat162float(featL[ad]);
            }
            sIn[ci][yy][xx] = v + sInit[yy][xx];
        }
        __syncthreads();
#pragma unroll 1
        for (int ci = 0; ci < 8; ci++)
#pragma unroll
            for (int ky = 0; ky < 3; ky++)
#pragma unroll
                for (int kx = 0; kx < 3; kx++)
                    acc += sIn[ci][r + ky][c + kx] * sWl[(ci0 + ci) * 9 + ky * 3 + kx];
        __syncthreads();
    }
    out[n * HWSZ + (ty * 16 + r) * 256 + (tx * 16 + c)] = acc;
}

// ---------------------------------------------------------------------------
extern "C" void kernel_launch(void* const* d_in, const int* in_sizes, int n_in,
                              void* d_out, int out_size) {
    (void)in_sizes; (void)n_in; (void)out_size;
    const float* x   = (const float*)d_in[0];
    const float* Wcs = (const float*)d_in[1];
    const float* Wi  = (const float*)d_in[2];
    const float* Wf  = (const float*)d_in[3];
    const float* Wb  = (const float*)d_in[4];
    const float* Wl  = (const float*)d_in[5];
    const float* aM  = (const float*)d_in[6];
    const float* aB  = (const float*)d_in[7];

    float* out     = (float*)d_out;
    float* csy     = out + 16 * HWSZ;
    float* initrec = csy + 16 * 256 * 64;

    void *pA = nullptr, *pB = nullptr, *pW = nullptr;
    cudaGetSymbolAddress(&pA, g_featA);
    cudaGetSymbolAddress(&pB, g_featB);
    cudaGetSymbolAddress(&pW, g_wblk);
    __nv_bfloat16* hiA = (__nv_bfloat16*)pA;
    __nv_bfloat16* loA = hiA + PLANE;
    __nv_bfloat16* hiB = (__nv_bfloat16*)pB;
    __nv_bfloat16* loB = hiB + PLANE;
    __nv_bfloat16* wblk = (__nv_bfloat16*)pW;

    cudaFuncSetAttribute(blk_mma<false>, cudaFuncAttributeMaxDynamicSharedMemorySize, SMEM_BLK);
    cudaFuncSetAttribute(blk_mma<true>,  cudaFuncAttributeMaxDynamicSharedMemorySize, SMEM_BLK);

    wprep_kernel<<<(9 * 64 * 200 + 255) / 256, 256>>>(Wb, wblk);
    cs_kernel<<<dim3(8, 16), 256>>>(x, Wcs, csy);
    init_kernel<<<dim3(8, 16), 256>>>(csy, Wi, initrec);
    first_kernel<<<dim3(16, 16, 16), 256>>>(initrec, Wf, aM, hiA, loA);

    for (int i = 0; i < 4; i++) {
        blk_mma<false><<<dim3(512, 16), 256, SMEM_BLK>>>(hiA, loA, wblk, aB, hiB, loB);
        blk_mma<true><<<dim3(512, 16), 256, SMEM_BLK>>>(hiB, loB, wblk, aB, hiA, loA);
    }
    last_kernel<<<dim3(16, 16, 16), 256>>>(hiA, loA, initrec, Wl, out);
}

// round 6
// speedup vs baseline: 1.6179x; 1.2639x over previous
#include <cuda_runtime.h>
#include <cuda_bf16.h>
#include <cstdint>

#define HWSZ 65536
#define FEAT (16*64*HWSZ)
#define PLANE ((size_t)16*HWSZ*64)

__device__ float g_featA[FEAT];
__device__ float g_featB[FEAT];
__device__ unsigned char g_wblk[147456];   // [tap 9][co 64][K 128] bf16, swizzled

#define SB_OFF 0
#define SA_OFF 147456                      // 4 slots x 2 planes x 9504B (66px x 144B)
#define SMEM_BLK (147456 + 4 * 19008)      // 223,488 B

__device__ __forceinline__ float prelu_f(float v, float a) { return v >= 0.f ? v : a * v; }

__device__ __forceinline__ uint32_t smem_u32(const void* p) {
    uint32_t a;
    asm("{ .reg .u64 t; cvta.to.shared.u64 t, %1; cvt.u32.u64 %0, t; }" : "=r"(a) : "l"(p));
    return a;
}
__device__ __forceinline__ void ldsm4(uint32_t* r, uint32_t addr) {
    asm volatile("ldmatrix.sync.aligned.m8n8.x4.shared.b16 {%0,%1,%2,%3}, [%4];"
                 : "=r"(r[0]), "=r"(r[1]), "=r"(r[2]), "=r"(r[3]) : "r"(addr));
}
__device__ __forceinline__ void mma16816(float* d, const uint32_t* a, uint32_t b0, uint32_t b1) {
    asm volatile("mma.sync.aligned.m16n8k16.row.col.f32.bf16.bf16.f32 "
                 "{%0,%1,%2,%3},{%4,%5,%6,%7},{%8,%9},{%0,%1,%2,%3};"
                 : "+f"(d[0]), "+f"(d[1]), "+f"(d[2]), "+f"(d[3])
                 : "r"(a[0]), "r"(a[1]), "r"(a[2]), "r"(a[3]), "r"(b0), "r"(b1));
}
__device__ __forceinline__ void cpa16(uint32_t dst, const void* src, int sz) {
    asm volatile("cp.async.cg.shared.global [%0], [%1], 16, %2;" :: "r"(dst), "l"(src), "r"(sz));
}
__device__ __forceinline__ void cpa16f(uint32_t dst, const void* src) {
    asm volatile("cp.async.cg.shared.global [%0], [%1], 16;" :: "r"(dst), "l"(src));
}
#define CPA_COMMIT() asm volatile("cp.async.commit_group;")
#define CPA_WAIT0()  asm volatile("cp.async.wait_group 0;")

// ---- weight prep: Wb fp32 -> swizzled [tap][co][K=128: wh(64)|wl(64)] ----
__global__ void wprep_kernel(const float* __restrict__ Wb, unsigned char* __restrict__ wsp) {
    int i = blockIdx.x * 256 + threadIdx.x;
    if (i >= 9 * 64 * 128) return;
    int k = i & 127, co = (i >> 7) & 63, tap = i >> 13;
    int ci = k & 63, seg = k >> 6;
    float w = Wb[co * 576 + ci * 9 + tap];
    __nv_bfloat16 h = __float2bfloat16(w);
    __nv_bfloat16 v = seg ? __float2bfloat16(w - __bfloat162float(h)) : h;
    int kb = 2 * k;
    int off = (kb & 128) | ((kb & 127) ^ ((co & 7) << 4));
    *(__nv_bfloat16*)(wsp + tap * 16384 + co * 256 + off) = v;
}

// ---------------- CS sampling conv (fp32) ----------------------------------
__global__ void cs_kernel(const float* __restrict__ x, const float* __restrict__ Wcs,
                          float* __restrict__ csy) {
    const int pg = blockIdx.x, n = blockIdx.y, f = threadIdx.x;
    __shared__ float sX[8][32];
    __shared__ float sW[256][33];
    float acc[8] = {};
    for (int k0 = 0; k0 < 1024; k0 += 32) {
        const int i = k0 >> 5;
        int p = threadIdx.x >> 5, kk = threadIdx.x & 31;
        sX[p][kk] = x[n * HWSZ + (pg * 32 + i) * 256 + p * 32 + kk];
        for (int e = threadIdx.x; e < 8192; e += 256)
            sW[e >> 5][e & 31] = Wcs[(e >> 5) * 1024 + k0 + (e & 31)];
        __syncthreads();
#pragma unroll
        for (int q = 0; q < 32; q++) {
            float w = sW[f][q];
#pragma unroll
            for (int pp = 0; pp < 8; pp++) acc[pp] += sX[pp][q] * w;
        }
        __syncthreads();
    }
#pragma unroll
    for (int pp = 0; pp < 8; pp++) csy[(n * 256 + f) * 64 + pg * 8 + pp] = acc[pp];
}

// ---------------- init reconstruction (fp32) -------------------------------
__global__ void init_kernel(const float* __restrict__ csy, const float* __restrict__ Wi,
                            float* __restrict__ initrec) {
    const int cb = blockIdx.x * 128, n = blockIdx.y;
    const int cg = threadIdx.x >> 3, pgl = threadIdx.x & 7;
    __shared__ float sX[32][64];
    __shared__ float sW[128][33];
    float acc[4][8] = {};
    for (int k0 = 0; k0 < 256; k0 += 32) {
        for (int e = threadIdx.x; e < 2048; e += 256)
            sX[e >> 6][e & 63] = csy[(n * 256 + k0 + (e >> 6)) * 64 + (e & 63)];
        for (int e = threadIdx.x; e < 4096; e += 256)
            sW[e >> 5][e & 31] = Wi[(cb + (e >> 5)) * 256 + k0 + (e & 31)];
        __syncthreads();
#pragma unroll
        for (int kk = 0; kk < 32; kk++) {
            float w0 = sW[cg*4+0][kk], w1 = sW[cg*4+1][kk], w2 = sW[cg*4+2][kk], w3 = sW[cg*4+3][kk];
#pragma unroll
            for (int pp = 0; pp < 8; pp++) {
                float xv = sX[kk][pgl * 8 + pp];
                acc[0][pp] += w0*xv; acc[1][pp] += w1*xv; acc[2][pp] += w2*xv; acc[3][pp] += w3*xv;
            }
        }
        __syncthreads();
    }
#pragma unroll
    for (int jc = 0; jc < 4; jc++) {
        int c = cb + cg * 4 + jc, jj = c >> 5, ii = c & 31;
#pragma unroll
        for (int pp = 0; pp < 8; pp++) {
            int pos = pgl * 8 + pp, by = pos >> 3, bx = pos & 7;
            initrec[n * HWSZ + (by * 32 + ii) * 256 + (bx * 32 + jj)] = acc[jc][pp];
        }
    }
}

// ------- first conv 1->64 + PReLU -> hi/lo bf16 planes ---------------------
__global__ void first_kernel(const float* __restrict__ initrec, const float* __restrict__ Wf,
                             const float* __restrict__ aM,
                             __nv_bfloat16* __restrict__ outH, __nv_bfloat16* __restrict__ outL) {
    const int tx = blockIdx.x, ty = blockIdx.y, n = blockIdx.z;
    __shared__ float sI[18][18];
    __shared__ float sWf[576];
    for (int e = threadIdx.x; e < 324; e += 256) {
        int yy = e / 18, xx = e % 18, gy = ty * 16 - 1 + yy, gx = tx * 16 - 1 + xx;
        sI[yy][xx] = ((unsigned)gy < 256u && (unsigned)gx < 256u) ? initrec[n * HWSZ + gy * 256 + gx] : 0.f;
    }
    for (int e = threadIdx.x; e < 576; e += 256) sWf[e] = Wf[e];
    __syncthreads();
    const float a = aM[0];
    const int co = threadIdx.x & 63, pl = threadIdx.x >> 6;
    float wr[9];
#pragma unroll
    for (int k = 0; k < 9; k++) wr[k] = sWf[co * 9 + k];
    for (int pxi = 0; pxi < 64; pxi++) {
        int px = pxi * 4 + pl, r = px >> 4, c = px & 15;
        float s = 0.f;
#pragma unroll
        for (int ky = 0; ky < 3; ky++)
#pragma unroll
            for (int kx = 0; kx < 3; kx++) s += wr[ky * 3 + kx] * sI[r + ky][c + kx];
        s = prelu_f(s, a);
        __nv_bfloat16 h = __float2bfloat16(s);
        __nv_bfloat16 l = __float2bfloat16(s - __bfloat162float(h));
        size_t ad = ((size_t)(n * HWSZ + (ty * 16 + r) * 256 + tx * 16 + c)) * 64 + co;
        outH[ad] = h;
        outL[ad] = l;
    }
}

// ---------- res-block conv 64->64, multi-tile CTA, B resident --------------
// grid (64, 16): xc = bx&3 (64px col), yg = bx>>2 (16-row group). 256 thr, 8 warps.
__device__ __forceinline__ void load_row(uint32_t sb, const __nv_bfloat16* inH,
                                         const __nv_bfloat16* inL, int n, int y,
                                         int x0, int rel, int tid) {
    uint32_t base = sb + SA_OFF + (uint32_t)(rel & 3) * 19008;
    for (int idx = tid; idx < 1056; idx += 256) {
        int plane = idx >= 528;
        int i2 = plane ? idx - 528 : idx;
        int px = i2 >> 3, ch = i2 & 7;
        int gx = x0 - 1 + px;
        bool ok = (unsigned)y < 256u && (unsigned)gx < 256u;
        const __nv_bfloat16* bp = plane ? inL : inH;
        const __nv_bfloat16* sp = ok ? bp + ((size_t)(n * HWSZ + y * 256 + gx)) * 64 + ch * 8 : bp;
        cpa16(base + (uint32_t)plane * 9504 + px * 144 + ch * 16, sp, ok ? 16 : 0);
    }
}

template <bool RES>
__global__ void __launch_bounds__(256, 1) blk_mma(
    const __nv_bfloat16* __restrict__ inH, const __nv_bfloat16* __restrict__ inL,
    const unsigned char* __restrict__ wblk, const float* __restrict__ aB,
    __nv_bfloat16* __restrict__ outH, __nv_bfloat16* __restrict__ outL) {
    extern __shared__ unsigned char sm[];
    const uint32_t sb = smem_u32(sm);
    const int tid = threadIdx.x, w = tid >> 5, lane = tid & 31;
    const int n = blockIdx.y, x0 = (blockIdx.x & 3) * 64, y0 = (blockIdx.x >> 2) * 16;

    // B: all 9 taps, once per CTA
    {
        const uint4* s = (const uint4*)wblk;
        for (int i = tid; i < 9216; i += 256) cpa16f(sb + i * 16, s + i);
    }
    load_row(sb, inH, inL, n, y0 - 1, x0, 0, tid);
    load_row(sb, inH, inL, n, y0,     x0, 1, tid);
    load_row(sb, inH, inL, n, y0 + 1, x0, 2, tid);
    CPA_COMMIT();
    CPA_WAIT0();
    __syncthreads();

    // per-lane constants
    const int mf = w & 3, co0 = (w >> 2) * 32;
    const uint32_t pxoff = (uint32_t)((mf * 16 + (lane & 15)) * 144) + ((lane >> 4) & 1) * 16;
    const int co_l = (lane & 7) + ((lane >> 4) & 1) * 8;
    const int kb_l = ((lane >> 3) & 1) * 16;
    const int sx = (lane & 7) << 4;
    uint32_t offk[8];
#pragma unroll
    for (int j = 0; j < 8; j++) {
        int kb = j * 32 + kb_l;
        offk[j] = (uint32_t)((kb & 128) | ((kb & 127) ^ sx));
    }
    const uint32_t bbase = sb + (uint32_t)(co0 + co_l) * 256;
    const float a = aB[0];

    for (int t = 0; t < 16; t++) {
        if (t < 15) {
            load_row(sb, inH, inL, n, y0 + t + 2, x0, t + 3, tid);
            CPA_COMMIT();
        }
        float acc[4][4];
#pragma unroll
        for (int i = 0; i < 4; i++)
#pragma unroll
            for (int j = 0; j < 4; j++) acc[i][j] = 0.f;

#pragma unroll
        for (int ky = 0; ky < 3; ky++) {
            const uint32_t aRow = sb + SA_OFF + (uint32_t)((t + ky) & 3) * 19008 + pxoff;
#pragma unroll
            for (int kx = 0; kx < 3; kx++) {
                const uint32_t aH = aRow + kx * 144, aL = aH + 9504;
                uint32_t ah[4][4], al[4][4];
#pragma unroll
                for (int q = 0; q < 4; q++) {
                    ldsm4(ah[q], aH + q * 32);
                    ldsm4(al[q], aL + q * 32);
                }
                const uint32_t bt = bbase + (uint32_t)(ky * 3 + kx) * 16384;
#pragma unroll
                for (int np = 0; np < 2; np++) {
                    const uint32_t bb = bt + np * 4096;
#pragma unroll
                    for (int ks = 0; ks < 4; ks++) {   // wh: feeds ah and al terms
                        uint32_t b[4];
                        ldsm4(b, bb + offk[ks]);
                        mma16816(acc[np*2+0], ah[ks], b[0], b[1]);
                        mma16816(acc[np*2+1], ah[ks], b[2], b[3]);
                        mma16816(acc[np*2+0], al[ks], b[0], b[1]);
                        mma16816(acc[np*2+1], al[ks], b[2], b[3]);
                    }
#pragma unroll
                    for (int ks = 0; ks < 4; ks++) {   // wl: ah only
                        uint32_t b[4];
                        ldsm4(b, bb + offk[4 + ks]);
                        mma16816(acc[np*2+0], ah[ks], b[0], b[1]);
                        mma16816(acc[np*2+1], ah[ks], b[2], b[3]);
                    }
                }
            }
        }

        // epilogue: residual + PReLU + split store
        const int r0 = lane >> 2;
        const size_t rowbase = (size_t)(n * HWSZ + (y0 + t) * 256 + x0 + mf * 16);
#pragma unroll
        for (int h = 0; h < 2; h++) {
            size_t pa = (rowbase + r0 + h * 8) * 64 + co0 + (lane & 3) * 2;
#pragma unroll
            for (int nf = 0; nf < 4; nf++) {
                size_t ad = pa + nf * 8;
                float v0 = acc[nf][h * 2 + 0], v1 = acc[nf][h * 2 + 1];
                if (RES) {
                    uint32_t h2 = *(const uint32_t*)(outH + ad);
                    uint32_t l2 = *(const uint32_t*)(outL + ad);
                    v0 += __bfloat162float(__ushort_as_bfloat16((unsigned short)(h2 & 0xffff))) +
                          __bfloat162float(__ushort_as_bfloat16((unsigned short)(l2 & 0xffff)));
                    v1 += __bfloat162float(__ushort_as_bfloat16((unsigned short)(h2 >> 16))) +
                          __bfloat162float(__ushort_as_bfloat16((unsigned short)(l2 >> 16)));
                }
                v0 = prelu_f(v0, a);
                v1 = prelu_f(v1, a);
                __nv_bfloat16 h0 = __float2bfloat16(v0), h1 = __float2bfloat16(v1);
                __nv_bfloat16 l0 = __float2bfloat16(v0 - __bfloat162float(h0));
                __nv_bfloat16 l1 = __float2bfloat16(v1 - __bfloat162float(h1));
                *(uint32_t*)(outH + ad) = (uint32_t)__bfloat16_as_ushort(h0) |
                                          ((uint32_t)__bfloat16_as_ushort(h1) << 16);
                *(uint32_t*)(outL + ad) = (uint32_t)__bfloat16_as_ushort(l0) |
                                          ((uint32_t)__bfloat16_as_ushort(l1) << 16);
            }
        }
        CPA_WAIT0();
        __syncthreads();
    }
}

// --------- last conv: (feat planes + initrec) -> 1 channel -----------------
__global__ void last_kernel(const __nv_bfloat16* __restrict__ featH,
                            const __nv_bfloat16* __restrict__ featL,
                            const float* __restrict__ initrec,
                            const float* __restrict__ Wl, float* __restrict__ out) {
    const int tx = blockIdx.x, ty = blockIdx.y, n = blockIdx.z;
    __shared__ float sInit[18][18];
    __shared__ float sIn[8][18][20];
    __shared__ float sWl[576];
    for (int e = threadIdx.x; e < 324; e += 256) {
        int yy = e / 18, xx = e % 18, gy = ty * 16 - 1 + yy, gx = tx * 16 - 1 + xx;
        sInit[yy][xx] = ((unsigned)gy < 256u && (unsigned)gx < 256u) ? initrec[n * HWSZ + gy * 256 + gx] : 0.f;
    }
    for (int e = threadIdx.x; e < 576; e += 256) sWl[e] = Wl[e];
    __syncthreads();
    const int r = threadIdx.x >> 4, c = threadIdx.x & 15;
    float acc = 0.f;
    for (int ci0 = 0; ci0 < 64; ci0 += 8) {
        for (int e = threadIdx.x; e < 2592; e += 256) {
            int px = e >> 3, ci = e & 7, yy = px / 18, xx = px % 18;
            int gy = ty * 16 - 1 + yy, gx = tx * 16 - 1 + xx;
            float v = 0.f;
            if ((unsigned)gy < 256u && (unsigned)gx < 256u) {
                size_t ad = (size_t)(n * HWSZ + gy * 256 + gx) * 64 + ci0 + ci;
                v = __bfloat162float(featH[ad]) + __bfloat162float(featL[ad]);
            }
            sIn[ci][yy][xx] = v + sInit[yy][xx];
        }
        __syncthreads();
#pragma unroll 1
        for (int ci = 0; ci < 8; ci++)
#pragma unroll
            for (int ky = 0; ky < 3; ky++)
#pragma unroll
                for (int kx = 0; kx < 3; kx++)
                    acc += sIn[ci][r + ky][c + kx] * sWl[(ci0 + ci) * 9 + ky * 3 + kx];
        __syncthreads();
    }
    out[n * HWSZ + (ty * 16 + r) * 256 + (tx * 16 + c)] = acc;
}

// ---------------------------------------------------------------------------
extern "C" void kernel_launch(void* const* d_in, const int* in_sizes, int n_in,
                              void* d_out, int out_size) {
    (void)in_sizes; (void)n_in; (void)out_size;
    const float* x   = (const float*)d_in[0];
    const float* Wcs = (const float*)d_in[1];
    const float* Wi  = (const float*)d_in[2];
    const float* Wf  = (const float*)d_in[3];
    const float* Wb  = (const float*)d_in[4];
    const float* Wl  = (const float*)d_in[5];
    const float* aM  = (const float*)d_in[6];
    const float* aB  = (const float*)d_in[7];

    float* out     = (float*)d_out;
    float* csy     = out + 16 * HWSZ;
    float* initrec = csy + 16 * 256 * 64;

    void *pA = nullptr, *pB = nullptr, *pW = nullptr;
    cudaGetSymbolAddress(&pA, g_featA);
    cudaGetSymbolAddress(&pB, g_featB);
    cudaGetSymbolAddress(&pW, g_wblk);
    __nv_bfloat16* hiA = (__nv_bfloat16*)pA;
    __nv_bfloat16* loA = hiA + PLANE;
    __nv_bfloat16* hiB = (__nv_bfloat16*)pB;
    __nv_bfloat16* loB = hiB + PLANE;
    unsigned char* wblk = (unsigned char*)pW;

    cudaFuncSetAttribute(blk_mma<false>, cudaFuncAttributeMaxDynamicSharedMemorySize, SMEM_BLK);
    cudaFuncSetAttribute(blk_mma<true>,  cudaFuncAttributeMaxDynamicSharedMemorySize, SMEM_BLK);

    wprep_kernel<<<(9 * 64 * 128 + 255) / 256, 256>>>(Wb, wblk);
    cs_kernel<<<dim3(8, 16), 256>>>(x, Wcs, csy);
    init_kernel<<<dim3(8, 16), 256>>>(csy, Wi, initrec);
    first_kernel<<<dim3(16, 16, 16), 256>>>(initrec, Wf, aM, hiA, loA);

    for (int i = 0; i < 4; i++) {
        blk_mma<false><<<dim3(64, 16), 256, SMEM_BLK>>>(hiA, loA, wblk, aB, hiB, loB);
        blk_mma<true><<<dim3(64, 16), 256, SMEM_BLK>>>(hiB, loB, wblk, aB, hiA, loA);
    }
    last_kernel<<<dim3(16, 16, 16), 256>>>(hiA, loA, initrec, Wl, out);
}